// round 16
// baseline (speedup 1.0000x reference)
#include <cuda_runtime.h>
#include <cuda_fp16.h>
#include <cstdint>
#include <math.h>

#define BATCH 16
#define NNODE 2048
#define R_TOTAL (BATCH * NNODE)

// ---------------- scratch (device globals) ----------------
__device__ __align__(16) float  g_bufC[R_TOTAL * 22 * 16];
__device__ __align__(16) __half g_Ah[NNODE * NNODE];
__device__ __align__(16) __half g_Uh[(size_t)BATCH * 352 * NNODE];
__device__ __align__(16) __half g_Ch[(size_t)BATCH * 2048 * 352];
__device__ __align__(16) __half g_Xh[(size_t)R_TOTAL * 20 * 64];
__device__ __align__(16) __half g_Yh[(size_t)R_TOTAL * 18 * 64];
__device__ __align__(16) __half g_Wth[4 * 128 * 192];
__device__ __align__(16) float2 g_Wp[3 * 64 * 64];
__device__ __align__(16) float2 g_bp[5][64];

// ---------------- helpers ----------------
__device__ __forceinline__ unsigned long long pk2(float lo, float hi) {
    unsigned long long r;
    asm("mov.b64 %0, {%1, %2};" : "=l"(r) : "f"(lo), "f"(hi));
    return r;
}
__device__ __forceinline__ void fma2(unsigned long long& d, unsigned long long a,
                                     unsigned long long b) {
    asm("fma.rn.f32x2 %0, %1, %2, %0;" : "+l"(d) : "l"(a), "l"(b));
}
__device__ __forceinline__ float2 upk(unsigned long long v) {
    float lo, hi;
    asm("mov.b64 {%0, %1}, %2;" : "=f"(lo), "=f"(hi) : "l"(v));
    return make_float2(lo, hi);
}
__device__ __forceinline__ float fast_sigmoid(float x) {
    float t;
    asm("tanh.approx.f32 %0, %1;" : "=f"(t) : "f"(0.5f * x));
    return fmaf(0.5f, t, 0.5f);
}
__device__ __forceinline__ uint32_t smem_u32(const void* p) {
    uint32_t a;
    asm("{ .reg .u64 t; cvta.to.shared.u64 t, %1; cvt.u32.u64 %0, t; }" : "=r"(a) : "l"(p));
    return a;
}
#define CP16(sa, gp) asm volatile("cp.async.ca.shared.global [%0], [%1], 16;" \
    :: "r"(sa), "l"(gp) : "memory")
#define CPCOMMIT() asm volatile("cp.async.commit_group;" ::: "memory")
#define CPWAIT2()  asm volatile("cp.async.wait_group 2;" ::: "memory")
#define CPWAIT1()  asm volatile("cp.async.wait_group 1;" ::: "memory")
#define CPWAIT0()  asm volatile("cp.async.wait_group 0;" ::: "memory")
#define LDSM4(r, a) asm volatile( \
    "ldmatrix.sync.aligned.m8n8.x4.shared.b16 {%0,%1,%2,%3}, [%4];" \
    : "=r"((r)[0]), "=r"((r)[1]), "=r"((r)[2]), "=r"((r)[3]) : "r"(a))
__device__ __forceinline__ void mma_f16(float* c, const uint32_t* a,
                                        uint32_t b0, uint32_t b1) {
    asm volatile(
        "mma.sync.aligned.m16n8k16.row.col.f32.f16.f16.f32 "
        "{%0,%1,%2,%3}, {%4,%5,%6,%7}, {%8,%9}, {%0,%1,%2,%3};"
        : "+f"(c[0]), "+f"(c[1]), "+f"(c[2]), "+f"(c[3])
        : "r"(a[0]), "r"(a[1]), "r"(a[2]), "r"(a[3]), "r"(b0), "r"(b1));
}

// pos(c) = (c&3)*16 + (c>>2);  inv(p) = (p>>4) + (p&15)*4

// ---------------- fused prep kernel ----------------
__device__ __forceinline__ void packWt_body(const float* __restrict__ W,
    const float* __restrict__ B3, __half* __restrict__ Wth,
    float2* __restrict__ bp, int CIN, int KM, int lb, int tid, int perm)
{
    const int K = 3 * CIN;
    const int i = lb * 256 + tid;
    if (i < 128 * KM) {
        int n = i / KM, k = i % KM;
        int kl = k;
        if (perm) {
            const int kk = k >> 6, pin = k & 63;
            kl = kk * 64 + (pin >> 4) + (pin & 15) * 4;
        }
        float v = 0.0f;
        if (kl < K) {
            int c = n >> 1, g = n & 1;
            int kk = kl / CIN, cin = kl % CIN;
            if (g == 0) v = W[(kk * CIN + cin) * 64 + c] + W[((3 + kk) * CIN + cin) * 64 + c];
            else        v = W[((6 + kk) * CIN + cin) * 64 + c];
        }
        Wth[i] = __float2half(v);
    }
    if (lb == 0 && tid < 64) bp[tid] = make_float2(B3[tid] + B3[64 + tid], B3[128 + tid]);
}

__global__ __launch_bounds__(256) void prep_kernel(
    const float* __restrict__ A, __half* __restrict__ Ah,
    const float* __restrict__ w1, const float* __restrict__ b1,
    const float* __restrict__ w2, const float* __restrict__ b2,
    const float* __restrict__ w3, const float* __restrict__ b3,
    const float* __restrict__ w4, const float* __restrict__ b4,
    const float* __restrict__ w5, const float* __restrict__ b5,
    float2* __restrict__ Wp, __half* __restrict__ Wth, float2* __restrict__ bp)
{
    const int bid = blockIdx.x, tid = threadIdx.x;
    {
        const int i = (bid * 256 + tid) * 4;
        const float4 v = *(const float4*)(A + i);
        *(__half2*)(Ah + i)     = __floats2half2_rn(v.x, v.y);
        *(__half2*)(Ah + i + 2) = __floats2half2_rn(v.z, v.w);
    }
    constexpr int WS = 128 * 192;
    if (bid < 96)        packWt_body(w3, b3, Wth + 1 * WS, bp + 2 * 64, 64, 192, bid, tid, 1);
    else if (bid < 192)  packWt_body(w5, b5, Wth + 3 * WS, bp + 4 * 64, 64, 192, bid - 96, tid, 1);
    else if (bid < 224)  packWt_body(w2, b2, Wth + 0 * WS, bp + 1 * 64, 16, 64, bid - 192, tid, 0);
    else if (bid < 256)  packWt_body(w4, b4, Wth + 2 * WS, bp + 3 * 64, 16, 64, bid - 224, tid, 0);
    else if (bid < 258) {
        const int i = (bid - 256) * 256 + tid;
        const int n = 3 * 2 * 64;
        if (i < n) Wp[i] = make_float2(w1[i] + w1[n + i], w1[2 * n + i]);
        if (i < 64) bp[i] = make_float2(b1[i] + b1[64 + i], b1[128 + i]);
    }
}

// U [z][2048][F] fp32 -> Ut fp16 [z][F][2048]
template <int F>
__global__ __launch_bounds__(256) void tsplitU_kernel(const float* __restrict__ U,
    __half* __restrict__ th)
{
    __shared__ float t[32][33];
    const int j0 = blockIdx.x * 32, f0 = blockIdx.y * 32, z = blockIdx.z;
    const int tx = threadIdx.x & 31, ty = threadIdx.x >> 5;
#pragma unroll
    for (int q = 0; q < 32; q += 8)
        t[ty + q][tx] = U[((size_t)z * 2048 + j0 + ty + q) * F + f0 + tx];
    __syncthreads();
#pragma unroll
    for (int q = 0; q < 32; q += 8) {
        size_t o = ((size_t)z * F + f0 + ty + q) * 2048 + j0 + tx;
        th[o] = __float2half(t[tx][ty + q]);
    }
}

// fused: u = Y @ theta2, transpose to fp16.  Y permuted fp16 [R,18,64]
__global__ __launch_bounds__(256) void theta_tsplit_kernel(
    const __half* __restrict__ Y, const float* __restrict__ theta,
    __half* __restrict__ Uh)
{
    __shared__ __align__(16) float ys[8 * 1156 + 4];
    __shared__ __align__(16) float thT[16 * 64];   // thT[p][m_permuted]
    const int tid = threadIdx.x;
    const int j0 = blockIdx.x * 8, z = blockIdx.y;
    const long rbase = (long)z * 2048 + j0;
    const uint4* src = (const uint4*)(Y + rbase * 1152);
    for (int i = tid; i < 8 * 144; i += 256) {
        int j = i / 144, q = i % 144;
        uint4 v = src[i];
        const __half2* hp = (const __half2*)&v;
        float* d = &ys[j * 1156 + q * 8];
#pragma unroll
        for (int e = 0; e < 4; ++e) {
            float2 f = __half22float2(hp[e]);
            d[2 * e] = f.x; d[2 * e + 1] = f.y;
        }
    }
    // thT[p][pos(m)] = theta[m][p]  (Y rows are in position space)
    for (int i = tid; i < 1024; i += 256) {
        int m = i >> 4, p = i & 15;
        thT[p * 64 + ((m & 3) * 16) + (m >> 2)] = theta[i];
    }
    __syncthreads();
    for (int o = tid; o < 288 * 8; o += 256) {
        int j = o & 7, f = o >> 3;
        int t = f >> 4, p = f & 15;
        const float4* yv = (const float4*)&ys[j * 1156 + t * 64];
        const float4* tv = (const float4*)&thT[p * 64];
        float s = 0.0f;
#pragma unroll
        for (int m4 = 0; m4 < 16; ++m4) {
            const float4 a = yv[m4], b = tv[m4];
            s = fmaf(a.x, b.x, s); s = fmaf(a.y, b.y, s);
            s = fmaf(a.z, b.z, s); s = fmaf(a.w, b.w, s);
        }
        Uh[((size_t)z * 288 + f) * 2048 + j0 + j] = __float2half(s);
    }
}

// ---------------- scalar timeblock (tb1, CIN=2) ----------------
template <int CIN, int TIN>
__global__ __launch_bounds__(128) void timeblock_kernel(
    const float* __restrict__ X, const float2* __restrict__ Wp,
    const float2* __restrict__ bp, const float* __restrict__ theta,
    float* __restrict__ Y)
{
    constexpr int TOUT = TIN - 2;
    constexpr int ROWS = 2;
    __shared__ __align__(16) float Xs[ROWS * TIN * CIN];
    __shared__ __align__(16) float Ys[ROWS * TOUT * 64];
    __shared__ __align__(16) float ThT[16 * 64];   // ThT[p][m]

    const int co = threadIdx.x, r = threadIdx.y;
    const int tid = r * 64 + co;
    const long row0 = (long)blockIdx.x * ROWS;
    {
        const float4* src = (const float4*)(X + row0 * (TIN * CIN));
        float4* dst = (float4*)Xs;
        for (int i = tid; i < ROWS * TIN * CIN / 4; i += 128) dst[i] = src[i];
    }
    for (int i = tid; i < 64 * 16; i += 128) {
        int m = i >> 4, p = i & 15;
        ThT[p * 64 + m] = theta[i];
    }
    __syncthreads();

    const float2 bb = bp[co];
    unsigned long long acc2[TOUT];
#pragma unroll
    for (int t = 0; t < TOUT; ++t) acc2[t] = pk2(bb.x, bb.y);

    const float* Xr = &Xs[r * TIN * CIN];
    for (int cin = 0; cin < CIN; ++cin) {
        unsigned long long xp[TIN];
#pragma unroll
        for (int t = 0; t < TIN; ++t) {
            const float v = Xr[t * CIN + cin];
            xp[t] = pk2(v, v);
        }
#pragma unroll
        for (int k = 0; k < 3; ++k) {
            const float2 wv = Wp[(k * CIN + cin) * 64 + co];
            const unsigned long long wp = pk2(wv.x, wv.y);
#pragma unroll
            for (int t = 0; t < TOUT; ++t) fma2(acc2[t], xp[t + k], wp);
        }
    }
#pragma unroll
    for (int t = 0; t < TOUT; ++t) {
        const float2 a = upk(acc2[t]);
        const float g = fast_sigmoid(a.y);
        float y = a.x * g;
        y = (y > 0.0f) ? y : 0.0f;
        Ys[(r * TOUT + t) * 64 + co] = y;
    }
    __syncthreads();
    for (int o = tid; o < ROWS * TOUT * 16; o += 128) {
        const int p = o & 15, t = (o >> 4) % TOUT, rr = o / (16 * TOUT);
        const float4* yv = (const float4*)&Ys[(rr * TOUT + t) * 64];
        const float4* tv = (const float4*)&ThT[p * 64];
        float s = 0.0f;
#pragma unroll
        for (int m4 = 0; m4 < 16; ++m4) {
            const float4 a = yv[m4], b = tv[m4];
            s = fmaf(a.x, b.x, s); s = fmaf(a.y, b.y, s);
            s = fmaf(a.z, b.z, s); s = fmaf(a.w, b.w, s);
        }
        Y[(row0 + rr) * (long)(TOUT * 16) + t * 16 + p] = s;
    }
}

// ---------------- conv-as-mma gated timeblock (3-stage X ring) --------------
template <int CIN, int TIN, int G, int S>
__global__ __launch_bounds__(256) void convmma_kernel(
    const __half* __restrict__ Xg, const __half* __restrict__ Whg,
    const float2* __restrict__ bp, __half* __restrict__ Yh)
{
    constexpr int TOUT = TIN - 2;
    constexpr int K = 3 * CIN;
    constexpr int KM = (K + 31) / 32 * 32;
    constexpr int KP = KM + 8;
    constexpr int TS = CIN + 8;
    constexpr int ROWEL = TIN * TS;
    constexpr int MROWS = G * TOUT;
    constexpr int XSZ = (G * ROWEL + 32) * 2;

    constexpr uint32_t WH = 3 * XSZ;
    constexpr uint32_t BIAS = WH + 128 * KP * 2;

    extern __shared__ __align__(128) char sm[];
    const uint32_t sb = smem_u32(sm);
    const int tid = threadIdx.x, w = tid >> 5, lane = tid & 31;
    const long base_r0 = (long)blockIdx.x * (G * S);

    constexpr int WCH = 128 * KM / 8;
    for (int i = tid; i < WCH; i += 256) {
        const int n = i / (KM / 8), kc = i % (KM / 8);
        CP16(sb + WH + (uint32_t)(n * KP + kc * 8) * 2, Whg + (size_t)n * KM + kc * 8);
    }

#define STAGE_X(bufidx, slab) do {                                             \
    const long r0_ = base_r0 + (long)(slab) * G;                               \
    const uint32_t bo_ = (uint32_t)(bufidx) * XSZ;                             \
    for (int i = tid; i < G * TIN * CIN / 8; i += 256) {                       \
        const int r_ = i / (TIN * CIN / 8);                                    \
        const int rem_ = i % (TIN * CIN / 8);                                  \
        const int t_ = rem_ / (CIN / 8);                                       \
        const int c8_ = rem_ % (CIN / 8);                                      \
        long gr_ = r0_ + r_; if (gr_ >= R_TOTAL) gr_ = R_TOTAL - 1;            \
        CP16(sb + bo_ + (uint32_t)(r_ * ROWEL + t_ * TS + c8_ * 8) * 2,        \
             Xg + (size_t)gr_ * (TIN * CIN) + t_ * CIN + c8_ * 8);             \
    }                                                                          \
    CPCOMMIT();                                                                \
} while (0)

    STAGE_X(0, 0);
    if (S > 1) STAGE_X(1, 1);
    if (tid < 64) *(float2*)(sm + BIAS + tid * 8) = bp[tid];
    if (tid < 32) {
#pragma unroll
        for (int b = 0; b < 3; ++b)
            ((__half*)(sm + (uint32_t)b * XSZ))[G * ROWEL + tid] = __float2half(0.0f);
    }

    const int mA = w * 16 + (lane & 15);
    int rrA = mA / TOUT, ttA = mA % TOUT;
    if (mA >= MROWS) { rrA = 0; ttA = 0; }
    const uint32_t abase = (uint32_t)(rrA * ROWEL + ttA * TS) * 2;
    const int hi8 = (lane >> 4) * 8;
    const uint32_t bbase = (uint32_t)((lane & 7) * KP * 2 + (lane >> 3) * 16);
    const int rE = w * 16 + (lane >> 2);
    const int ql = lane & 3;

    int sidx = 0;
    for (int s = 0; s < S; ++s) {
        if (s + 1 < S) CPWAIT1(); else CPWAIT0();
        __syncthreads();
        if (s + 2 < S) {
            STAGE_X((sidx + 2) % 3, s + 2);
        }

        const uint32_t xb = sb + (uint32_t)sidx * XSZ;
        float acc[16][4];
#pragma unroll
        for (int nt = 0; nt < 16; ++nt)
#pragma unroll
            for (int q = 0; q < 4; ++q) acc[nt][q] = 0.0f;

#pragma unroll
        for (int kc = 0; kc < KM / 32; ++kc) {
            uint32_t ah[2][4];
#pragma unroll
            for (int s2 = 0; s2 < 2; ++s2) {
                const int e0 = (2 * kc + s2) * 16 + hi8;
                const uint32_t off = (uint32_t)((e0 / CIN) * TS + (e0 % CIN)) * 2;
                LDSM4(ah[s2], xb + abase + off);
            }
#pragma unroll
            for (int nt = 0; nt < 16; ++nt) {
                uint32_t bh[4];
                LDSM4(bh, sb + WH + bbase + (uint32_t)(nt * 8 * KP * 2 + kc * 64));
                mma_f16(acc[nt], ah[0], bh[0], bh[1]);
                mma_f16(acc[nt], ah[1], bh[2], bh[3]);
            }
        }

        const long r0s = base_r0 + (long)s * G;
#pragma unroll
        for (int hf = 0; hf < 2; ++hf) {
            const int m = rE + hf * 8;
            const int rr = m / TOUT, tt = m % TOUT;
            const long gr = r0s + rr;
            if (m < MROWS && gr < R_TOTAL) {
                uint32_t pkd[8];
#pragma unroll
                for (int j = 0; j < 8; ++j) {
                    float yy[2];
#pragma unroll
                    for (int h = 0; h < 2; ++h) {
                        const int nt = 2 * j + h;
                        const int c = nt * 4 + ql;
                        const float2 bb = *(const float2*)(sm + BIAS + c * 8);
                        const float temp = acc[nt][hf * 2 + 0] + bb.x;
                        const float gate = acc[nt][hf * 2 + 1] + bb.y;
                        float y = temp * fast_sigmoid(gate);
                        yy[h] = (y > 0.0f) ? y : 0.0f;
                    }
                    __half2 h2 = __floats2half2_rn(yy[0], yy[1]);
                    pkd[j] = *(uint32_t*)&h2;
                }
                __half* dst = Yh + ((size_t)gr * TOUT + tt) * 64 + ql * 16;
                *(uint4*)dst       = make_uint4(pkd[0], pkd[1], pkd[2], pkd[3]);
                *(uint4*)(dst + 8) = make_uint4(pkd[4], pkd[5], pkd[6], pkd[7]);
            }
        }
        sidx = (sidx + 1) % 3;
    }
#undef STAGE_X
}

// ------- einsum GEMM: 4-stage cp.async ring, warps 2m x 4n, BM=BN=128 -------
template <int F>
__global__ __launch_bounds__(256, 2) void gemm_mma_kernel(
    const __half* __restrict__ Ah_g, const __half* __restrict__ Uh_g,
    __half* __restrict__ Ch_g)
{
    constexpr uint32_t BH = 128 * 80;        // 10240
    constexpr uint32_t STG = 2 * BH;         // 20480 B/stage
    extern __shared__ __align__(128) char smc[];
    const uint32_t sb = smem_u32(smc);

    const int tid = threadIdx.x, w = tid >> 5, lane = tid & 31;
    const int wm = w >> 2, wn = w & 3;
    const int m0 = blockIdx.x * 128, n0 = blockIdx.y * 128;

    const __half* Ab = Ah_g + (size_t)m0 * 2048;
    const __half* Bb = Uh_g + (size_t)n0 * 2048;

    const int ra = tid >> 1;
    const uint32_t acb = (tid & 1) * 32;
    const int ace = (tid & 1) * 16;

#define LOAD_STAGE(buf, k0) do {                                               \
    const uint32_t st_ = sb + (uint32_t)(buf) * STG;                           \
    CP16(st_ + ra * 80 + acb,           Ab + (size_t)ra * 2048 + (k0) + ace);  \
    CP16(st_ + ra * 80 + acb + 16,      Ab + (size_t)ra * 2048 + (k0) + ace + 8);\
    CP16(st_ + BH + ra * 80 + acb,      Bb + (size_t)ra * 2048 + (k0) + ace);  \
    CP16(st_ + BH + ra * 80 + acb + 16, Bb + (size_t)ra * 2048 + (k0) + ace + 8);\
    CPCOMMIT();                                                                \
} while (0)

    float acc[4][4][4];
#pragma unroll
    for (int mi = 0; mi < 4; ++mi)
#pragma unroll
        for (int ni = 0; ni < 4; ++ni)
#pragma unroll
            for (int q = 0; q < 4; ++q) acc[mi][ni][q] = 0.0f;

    LOAD_STAGE(0, 0);
    LOAD_STAGE(1, 32);
    LOAD_STAGE(2, 64);
    const uint32_t aoff = (uint32_t)((wm * 64 + (lane & 15)) * 80 + (lane >> 4) * 16);
    const uint32_t boff = (uint32_t)((wn * 32 + (lane & 7)) * 80 + (lane >> 3) * 16);

    int sidx = 0;
    for (int it = 0; it < 64; ++it) {
        if (it + 2 < 64) CPWAIT2();
        else if (it + 1 < 64) CPWAIT1();
        else CPWAIT0();
        __syncthreads();
        if (it + 3 < 64) LOAD_STAGE((sidx + 3) & 3, (it + 3) * 32);

        const uint32_t st = sb + (uint32_t)sidx * STG;
        uint32_t bF[4][4];
#pragma unroll
        for (int ni = 0; ni < 4; ++ni)
            LDSM4(bF[ni], st + BH + boff + ni * 8 * 80);
#pragma unroll
        for (int mi = 0; mi < 4; ++mi) {
            uint32_t aF[2][4];
            LDSM4(aF[0], st + aoff + mi * 16 * 80);
            LDSM4(aF[1], st + aoff + mi * 16 * 80 + 32);
#pragma unroll
            for (int ni = 0; ni < 4; ++ni) {
                mma_f16(acc[mi][ni], aF[0], bF[ni][0], bF[ni][1]);
                mma_f16(acc[mi][ni], aF[1], bF[ni][2], bF[ni][3]);
            }
        }
        sidx = (sidx + 1) & 3;
    }

    const int cbase = 2 * (lane & 3);
#pragma unroll
    for (int mi = 0; mi < 4; ++mi) {
        const int mr = m0 + wm * 64 + mi * 16 + (lane >> 2);
#pragma unroll
        for (int ni = 0; ni < 4; ++ni) {
            const int n = n0 + wn * 32 + ni * 8 + cbase;
            const int z = n / F, f = n - z * F;
            __half* H0 = Ch_g + ((size_t)z * 2048 + mr) * F + f;
            *(__half2*)H0 = __floats2half2_rn(fmaxf(acc[mi][ni][0], 0.0f),
                                              fmaxf(acc[mi][ni][1], 0.0f));
            *(__half2*)(H0 + 8 * (size_t)F) =
                __floats2half2_rn(fmaxf(acc[mi][ni][2], 0.0f),
                                  fmaxf(acc[mi][ni][3], 0.0f));
        }
    }
#undef LOAD_STAGE
}

// ---------------- FC (fp16 permuted input) + copy ----------------
__global__ __launch_bounds__(256) void fc_kernel(const __half* __restrict__ X,
    const float* __restrict__ W, const float* __restrict__ bias, float* __restrict__ out)
{
    const int lane = threadIdx.x;
    const long row = (long)blockIdx.x * blockDim.y + threadIdx.y;
    const __half2* x2 = (const __half2*)(X + row * 896);
    float acc[12];
#pragma unroll
    for (int p = 0; p < 12; ++p) acc[p] = 0.0f;
    for (int e2 = lane; e2 < 448; e2 += 32) {
        const float2 f = __half22float2(x2[e2]);
        const int t = e2 >> 5;
        const int p2 = (e2 & 31) * 2;
        const int cin = (p2 >> 4) + (p2 & 15) * 4;
        const float* w0 = W + (size_t)(t * 64 + cin) * 12;
#pragma unroll
        for (int p = 0; p < 12; ++p)
            acc[p] = fmaf(f.x, w0[p], fmaf(f.y, w0[48 + p], acc[p]));
    }
#pragma unroll
    for (int off = 16; off > 0; off >>= 1)
#pragma unroll
        for (int p = 0; p < 12; ++p) acc[p] += __shfl_down_sync(0xffffffffu, acc[p], off);
    if (lane == 0)
#pragma unroll
        for (int p = 0; p < 12; ++p) out[row * 12 + p] = acc[p] + bias[p];
}

__global__ __launch_bounds__(256) void copy4_kernel(const float4* __restrict__ s,
                                                    float4* __restrict__ d, int n4)
{
    const int i = blockIdx.x * blockDim.x + threadIdx.x;
    if (i < n4) d[i] = s[i];
}

// ---------------- launch ----------------
extern "C" void kernel_launch(void* const* d_in, const int* in_sizes, int n_in,
                              void* d_out, int out_size)
{
    const float* x       = (const float*)d_in[0];
    const float* A_hat   = (const float*)d_in[1];
    const float* tb1_w   = (const float*)d_in[2];
    const float* tb1_b   = (const float*)d_in[3];
    const float* theta1  = (const float*)d_in[4];
    const float* tb2_w   = (const float*)d_in[5];
    const float* tb2_b   = (const float*)d_in[6];
    const float* tb3_w   = (const float*)d_in[7];
    const float* tb3_b   = (const float*)d_in[8];
    const float* theta2  = (const float*)d_in[9];
    const float* tb4_w   = (const float*)d_in[10];
    const float* tb4_b   = (const float*)d_in[11];
    const float* tb5_w   = (const float*)d_in[12];
    const float* tb5_b   = (const float*)d_in[13];
    const float* fully_w = (const float*)d_in[14];
    const float* fully_b = (const float*)d_in[15];
    float* out = (float*)d_out;

    float *bufC;
    __half *Ah, *Uh, *Ch, *Xh, *Yh, *Wth;
    float2 *Wp, *bp;
    cudaGetSymbolAddress((void**)&bufC, g_bufC);
    cudaGetSymbolAddress((void**)&Ah, g_Ah);
    cudaGetSymbolAddress((void**)&Uh, g_Uh);
    cudaGetSymbolAddress((void**)&Ch, g_Ch);
    cudaGetSymbolAddress((void**)&Xh, g_Xh);
    cudaGetSymbolAddress((void**)&Yh, g_Yh);
    cudaGetSymbolAddress((void**)&Wth, g_Wth);
    cudaGetSymbolAddress((void**)&Wp, g_Wp);
    cudaGetSymbolAddress((void**)&bp, g_bp);

    constexpr int WS = 128 * 192;
    constexpr int SMEM_G = 4 * 20480;   // 81920
    constexpr int SM_TB2 = 3 * 6400  + 128 * 72 * 2  + 512;   // 38144
    constexpr int SM_TB3 = 3 * 20224 + 128 * 200 * 2 + 512;   // 112384
    constexpr int SM_TB4 = 3 * 6976  + 128 * 72 * 2  + 512;   // 39872
    constexpr int SM_TB5 = 3 * 20800 + 128 * 200 * 2 + 512;   // 114112
    cudaFuncSetAttribute(gemm_mma_kernel<352>, cudaFuncAttributeMaxDynamicSharedMemorySize, SMEM_G);
    cudaFuncSetAttribute(gemm_mma_kernel<288>, cudaFuncAttributeMaxDynamicSharedMemorySize, SMEM_G);
    cudaFuncSetAttribute(convmma_kernel<16, 22, 6, 8>, cudaFuncAttributeMaxDynamicSharedMemorySize, SM_TB2);
    cudaFuncSetAttribute(convmma_kernel<64, 20, 7, 8>, cudaFuncAttributeMaxDynamicSharedMemorySize, SM_TB3);
    cudaFuncSetAttribute(convmma_kernel<16, 18, 8, 8>, cudaFuncAttributeMaxDynamicSharedMemorySize, SM_TB4);
    cudaFuncSetAttribute(convmma_kernel<64, 16, 9, 8>, cudaFuncAttributeMaxDynamicSharedMemorySize, SM_TB5);

    // prep (1 launch)
    prep_kernel<<<NNODE * NNODE / 1024, 256>>>(A_hat, Ah,
        tb1_w, tb1_b, tb2_w, tb2_b, tb3_w, tb3_b, tb4_w, tb4_b, tb5_w, tb5_b,
        Wp, Wth, (float2*)bp);

    // block 1
    timeblock_kernel<2, 24><<<R_TOTAL / 2, dim3(64, 2)>>>(x, Wp, (float2*)bp + 0 * 64, theta1, bufC);
    tsplitU_kernel<352><<<dim3(64, 11, BATCH), 256>>>(bufC, Uh);
    gemm_mma_kernel<352><<<dim3(16, (BATCH * 352) / 128), 256, SMEM_G>>>(Ah, Uh, Ch);
    convmma_kernel<16, 22, 6, 8><<<(R_TOTAL + 47) / 48, 256, SM_TB2>>>(
        Ch, Wth + 0 * WS, (float2*)bp + 1 * 64, Xh);

    // block 2
    convmma_kernel<64, 20, 7, 8><<<(R_TOTAL + 55) / 56, 256, SM_TB3>>>(
        Xh, Wth + 1 * WS, (float2*)bp + 2 * 64, Yh);
    theta_tsplit_kernel<<<dim3(256, 16), 256>>>(Yh, theta2, Uh);
    gemm_mma_kernel<288><<<dim3(16, (BATCH * 288) / 128), 256, SMEM_G>>>(Ah, Uh, Ch);
    convmma_kernel<16, 18, 8, 8><<<R_TOTAL / 64, 256, SM_TB4>>>(
        Ch, Wth + 2 * WS, (float2*)bp + 3 * 64, Xh);

    // head
    convmma_kernel<64, 16, 9, 8><<<(R_TOTAL + 71) / 72, 256, SM_TB5>>>(
        Xh, Wth + 3 * WS, (float2*)bp + 4 * 64, Yh);
    fc_kernel<<<R_TOTAL / 8, dim3(32, 8)>>>(Yh, fully_w, fully_b, out);

    const int n4 = (NNODE * NNODE) / 4;
    copy4_kernel<<<(n4 + 255) / 256, 256>>>((const float4*)A_hat,
                                            (float4*)(out + (long)R_TOTAL * 12), n4);
}

// round 17
// speedup vs baseline: 1.1123x; 1.1123x over previous
#include <cuda_runtime.h>
#include <cuda_fp16.h>
#include <cstdint>
#include <math.h>

#define BATCH 16
#define NNODE 2048
#define R_TOTAL (BATCH * NNODE)

// ---------------- scratch (device globals) ----------------
__device__ __align__(16) float  g_bufC[R_TOTAL * 22 * 16];
__device__ __align__(16) __half g_Ah[NNODE * NNODE];
__device__ __align__(16) __half g_Uh[(size_t)BATCH * 352 * NNODE];
__device__ __align__(16) __half g_Ch[(size_t)BATCH * 2048 * 352];
__device__ __align__(16) __half g_Xh[(size_t)R_TOTAL * 20 * 64];
__device__ __align__(16) __half g_Yh[(size_t)R_TOTAL * 18 * 64];
__device__ __align__(16) __half g_Wth[4 * 128 * 192];
__device__ __align__(16) float2 g_Wp[3 * 64 * 64];
__device__ __align__(16) float2 g_bp[5][64];

// ---------------- helpers ----------------
__device__ __forceinline__ unsigned long long pk2(float lo, float hi) {
    unsigned long long r;
    asm("mov.b64 %0, {%1, %2};" : "=l"(r) : "f"(lo), "f"(hi));
    return r;
}
__device__ __forceinline__ void fma2(unsigned long long& d, unsigned long long a,
                                     unsigned long long b) {
    asm("fma.rn.f32x2 %0, %1, %2, %0;" : "+l"(d) : "l"(a), "l"(b));
}
__device__ __forceinline__ float2 upk(unsigned long long v) {
    float lo, hi;
    asm("mov.b64 {%0, %1}, %2;" : "=f"(lo), "=f"(hi) : "l"(v));
    return make_float2(lo, hi);
}
__device__ __forceinline__ float fast_sigmoid(float x) {
    float t;
    asm("tanh.approx.f32 %0, %1;" : "=f"(t) : "f"(0.5f * x));
    return fmaf(0.5f, t, 0.5f);
}
__device__ __forceinline__ uint32_t smem_u32(const void* p) {
    uint32_t a;
    asm("{ .reg .u64 t; cvta.to.shared.u64 t, %1; cvt.u32.u64 %0, t; }" : "=r"(a) : "l"(p));
    return a;
}
#define CP16(sa, gp) asm volatile("cp.async.ca.shared.global [%0], [%1], 16;" \
    :: "r"(sa), "l"(gp) : "memory")
#define CPCOMMIT() asm volatile("cp.async.commit_group;" ::: "memory")
#define CPWAIT1()  asm volatile("cp.async.wait_group 1;" ::: "memory")
#define CPWAIT0()  asm volatile("cp.async.wait_group 0;" ::: "memory")
#define LDSM4(r, a) asm volatile( \
    "ldmatrix.sync.aligned.m8n8.x4.shared.b16 {%0,%1,%2,%3}, [%4];" \
    : "=r"((r)[0]), "=r"((r)[1]), "=r"((r)[2]), "=r"((r)[3]) : "r"(a))
__device__ __forceinline__ void mma_f16(float* c, const uint32_t* a,
                                        uint32_t b0, uint32_t b1) {
    asm volatile(
        "mma.sync.aligned.m16n8k16.row.col.f32.f16.f16.f32 "
        "{%0,%1,%2,%3}, {%4,%5,%6,%7}, {%8,%9}, {%0,%1,%2,%3};"
        : "+f"(c[0]), "+f"(c[1]), "+f"(c[2]), "+f"(c[3])
        : "r"(a[0]), "r"(a[1]), "r"(a[2]), "r"(a[3]), "r"(b0), "r"(b1));
}

// pos(c) = (c&3)*16 + (c>>2);  inv(p) = (p>>4) + (p&15)*4

// ---------------- fused prep kernel (+ A_hat passthrough copy) -------------
__device__ __forceinline__ void packWt_body(const float* __restrict__ W,
    const float* __restrict__ B3, __half* __restrict__ Wth,
    float2* __restrict__ bp, int CIN, int KM, int lb, int tid, int perm)
{
    const int K = 3 * CIN;
    const int i = lb * 256 + tid;
    if (i < 128 * KM) {
        int n = i / KM, k = i % KM;
        int kl = k;
        if (perm) {
            const int kk = k >> 6, pin = k & 63;
            kl = kk * 64 + (pin >> 4) + (pin & 15) * 4;
        }
        float v = 0.0f;
        if (kl < K) {
            int c = n >> 1, g = n & 1;
            int kk = kl / CIN, cin = kl % CIN;
            if (g == 0) v = W[(kk * CIN + cin) * 64 + c] + W[((3 + kk) * CIN + cin) * 64 + c];
            else        v = W[((6 + kk) * CIN + cin) * 64 + c];
        }
        Wth[i] = __float2half(v);
    }
    if (lb == 0 && tid < 64) bp[tid] = make_float2(B3[tid] + B3[64 + tid], B3[128 + tid]);
}

__global__ __launch_bounds__(256) void prep_kernel(
    const float* __restrict__ A, __half* __restrict__ Ah,
    const float* __restrict__ w1, const float* __restrict__ b1,
    const float* __restrict__ w2, const float* __restrict__ b2,
    const float* __restrict__ w3, const float* __restrict__ b3,
    const float* __restrict__ w4, const float* __restrict__ b4,
    const float* __restrict__ w5, const float* __restrict__ b5,
    float2* __restrict__ Wp, __half* __restrict__ Wth, float2* __restrict__ bp,
    float* __restrict__ outA)
{
    const int bid = blockIdx.x, tid = threadIdx.x;
    {
        const int i = (bid * 256 + tid) * 4;
        const float4 v = *(const float4*)(A + i);
        *(__half2*)(Ah + i)     = __floats2half2_rn(v.x, v.y);
        *(__half2*)(Ah + i + 2) = __floats2half2_rn(v.z, v.w);
        *(float4*)(outA + i) = v;    // A_hat passthrough into out tail
    }
    constexpr int WS = 128 * 192;
    if (bid < 96)        packWt_body(w3, b3, Wth + 1 * WS, bp + 2 * 64, 64, 192, bid, tid, 1);
    else if (bid < 192)  packWt_body(w5, b5, Wth + 3 * WS, bp + 4 * 64, 64, 192, bid - 96, tid, 1);
    else if (bid < 224)  packWt_body(w2, b2, Wth + 0 * WS, bp + 1 * 64, 16, 64, bid - 192, tid, 0);
    else if (bid < 256)  packWt_body(w4, b4, Wth + 2 * WS, bp + 3 * 64, 16, 64, bid - 224, tid, 0);
    else if (bid < 258) {
        const int i = (bid - 256) * 256 + tid;
        const int n = 3 * 2 * 64;
        if (i < n) Wp[i] = make_float2(w1[i] + w1[n + i], w1[2 * n + i]);
        if (i < 64) bp[i] = make_float2(b1[i] + b1[64 + i], b1[128 + i]);
    }
}

// U [z][2048][F] fp32 -> Ut fp16 [z][F][2048]
template <int F>
__global__ __launch_bounds__(256) void tsplitU_kernel(const float* __restrict__ U,
    __half* __restrict__ th)
{
    __shared__ float t[32][33];
    const int j0 = blockIdx.x * 32, f0 = blockIdx.y * 32, z = blockIdx.z;
    const int tx = threadIdx.x & 31, ty = threadIdx.x >> 5;
#pragma unroll
    for (int q = 0; q < 32; q += 8)
        t[ty + q][tx] = U[((size_t)z * 2048 + j0 + ty + q) * F + f0 + tx];
    __syncthreads();
#pragma unroll
    for (int q = 0; q < 32; q += 8) {
        size_t o = ((size_t)z * F + f0 + ty + q) * 2048 + j0 + tx;
        th[o] = __float2half(t[tx][ty + q]);
    }
}

// fused: u = Y @ theta2, transpose to fp16.  Y permuted fp16 [R,18,64]
__global__ __launch_bounds__(256) void theta_tsplit_kernel(
    const __half* __restrict__ Y, const float* __restrict__ theta,
    __half* __restrict__ Uh)
{
    __shared__ float ys[8 * 1156 + 4];
    __shared__ float th[64 * 16];
    const int tid = threadIdx.x;
    const int j0 = blockIdx.x * 8, z = blockIdx.y;
    const long rbase = (long)z * 2048 + j0;
    const uint4* src = (const uint4*)(Y + rbase * 1152);
    for (int i = tid; i < 8 * 144; i += 256) {
        int j = i / 144, q = i % 144;
        uint4 v = src[i];
        const __half2* hp = (const __half2*)&v;
        float* d = &ys[j * 1156 + q * 8];
#pragma unroll
        for (int e = 0; e < 4; ++e) {
            float2 f = __half22float2(hp[e]);
            d[2 * e] = f.x; d[2 * e + 1] = f.y;
        }
    }
    // th[pos(m)][p] = theta[m][p]  (Y rows are in position space)
    for (int i = tid; i < 1024; i += 256) {
        int m = i >> 4, p = i & 15;
        th[(((m & 3) * 16) + (m >> 2)) * 16 + p] = theta[i];
    }
    __syncthreads();
    for (int o = tid; o < 288 * 8; o += 256) {
        int j = o & 7, f = o >> 3;
        int t = f >> 4, p = f & 15;
        const float* yr = &ys[j * 1156 + t * 64];
        float s = 0.0f;
#pragma unroll
        for (int m = 0; m < 64; ++m) s = fmaf(yr[m], th[m * 16 + p], s);
        Uh[((size_t)z * 288 + f) * 2048 + j0 + j] = __float2half(s);
    }
}

// ---------------- scalar timeblock (tb1, CIN=2) ----------------
template <int CIN, int TIN>
__global__ __launch_bounds__(128) void timeblock_kernel(
    const float* __restrict__ X, const float2* __restrict__ Wp,
    const float2* __restrict__ bp, const float* __restrict__ theta,
    float* __restrict__ Y)
{
    constexpr int TOUT = TIN - 2;
    constexpr int ROWS = 2;
    __shared__ __align__(16) float Xs[ROWS * TIN * CIN];
    __shared__ __align__(16) float Ys[ROWS * TOUT * 64];
    __shared__ __align__(16) float Ths[64 * 16];

    const int co = threadIdx.x, r = threadIdx.y;
    const int tid = r * 64 + co;
    const long row0 = (long)blockIdx.x * ROWS;
    {
        const float4* src = (const float4*)(X + row0 * (TIN * CIN));
        float4* dst = (float4*)Xs;
        for (int i = tid; i < ROWS * TIN * CIN / 4; i += 128) dst[i] = src[i];
    }
    for (int i = tid; i < 64 * 16; i += 128) Ths[i] = theta[i];
    __syncthreads();

    const float2 bb = bp[co];
    unsigned long long acc2[TOUT];
#pragma unroll
    for (int t = 0; t < TOUT; ++t) acc2[t] = pk2(bb.x, bb.y);

    const float* Xr = &Xs[r * TIN * CIN];
    for (int cin = 0; cin < CIN; ++cin) {
        unsigned long long xp[TIN];
#pragma unroll
        for (int t = 0; t < TIN; ++t) {
            const float v = Xr[t * CIN + cin];
            xp[t] = pk2(v, v);
        }
#pragma unroll
        for (int k = 0; k < 3; ++k) {
            const float2 wv = Wp[(k * CIN + cin) * 64 + co];
            const unsigned long long wp = pk2(wv.x, wv.y);
#pragma unroll
            for (int t = 0; t < TOUT; ++t) fma2(acc2[t], xp[t + k], wp);
        }
    }
#pragma unroll
    for (int t = 0; t < TOUT; ++t) {
        const float2 a = upk(acc2[t]);
        const float g = fast_sigmoid(a.y);
        float y = a.x * g;
        y = (y > 0.0f) ? y : 0.0f;
        Ys[(r * TOUT + t) * 64 + co] = y;
    }
    __syncthreads();
    for (int o = tid; o < ROWS * TOUT * 16; o += 128) {
        const int p = o & 15, t = (o >> 4) % TOUT, rr = o / (16 * TOUT);
        float s = 0.0f;
#pragma unroll
        for (int m = 0; m < 64; ++m)
            s = fmaf(Ys[(rr * TOUT + t) * 64 + m], Ths[m * 16 + p], s);
        Y[(row0 + rr) * (long)(TOUT * 16) + t * 16 + p] = s;
    }
}

// ---------------- conv-as-mma gated timeblock (3-stage X ring) --------------
template <int CIN, int TIN, int G, int S>
__global__ __launch_bounds__(256) void convmma_kernel(
    const __half* __restrict__ Xg, const __half* __restrict__ Whg,
    const float2* __restrict__ bp, __half* __restrict__ Yh)
{
    constexpr int TOUT = TIN - 2;
    constexpr int K = 3 * CIN;
    constexpr int KM = (K + 31) / 32 * 32;
    constexpr int KP = KM + 8;
    constexpr int TS = CIN + 8;
    constexpr int ROWEL = TIN * TS;
    constexpr int MROWS = G * TOUT;
    constexpr int XSZ = (G * ROWEL + 32) * 2;

    constexpr uint32_t WH = 3 * XSZ;
    constexpr uint32_t BIAS = WH + 128 * KP * 2;

    extern __shared__ __align__(128) char sm[];
    const uint32_t sb = smem_u32(sm);
    const int tid = threadIdx.x, w = tid >> 5, lane = tid & 31;
    const long base_r0 = (long)blockIdx.x * (G * S);

    constexpr int WCH = 128 * KM / 8;
    for (int i = tid; i < WCH; i += 256) {
        const int n = i / (KM / 8), kc = i % (KM / 8);
        CP16(sb + WH + (uint32_t)(n * KP + kc * 8) * 2, Whg + (size_t)n * KM + kc * 8);
    }

#define STAGE_X(bufidx, slab) do {                                             \
    const long r0_ = base_r0 + (long)(slab) * G;                               \
    const uint32_t bo_ = (uint32_t)(bufidx) * XSZ;                             \
    for (int i = tid; i < G * TIN * CIN / 8; i += 256) {                       \
        const int r_ = i / (TIN * CIN / 8);                                    \
        const int rem_ = i % (TIN * CIN / 8);                                  \
        const int t_ = rem_ / (CIN / 8);                                       \
        const int c8_ = rem_ % (CIN / 8);                                      \
        long gr_ = r0_ + r_; if (gr_ >= R_TOTAL) gr_ = R_TOTAL - 1;            \
        CP16(sb + bo_ + (uint32_t)(r_ * ROWEL + t_ * TS + c8_ * 8) * 2,        \
             Xg + (size_t)gr_ * (TIN * CIN) + t_ * CIN + c8_ * 8);             \
    }                                                                          \
    CPCOMMIT();                                                                \
} while (0)

    STAGE_X(0, 0);
    if (S > 1) STAGE_X(1, 1);
    if (tid < 64) *(float2*)(sm + BIAS + tid * 8) = bp[tid];
    if (tid < 32) {
#pragma unroll
        for (int b = 0; b < 3; ++b)
            ((__half*)(sm + (uint32_t)b * XSZ))[G * ROWEL + tid] = __float2half(0.0f);
    }

    const int mA = w * 16 + (lane & 15);
    int rrA = mA / TOUT, ttA = mA % TOUT;
    if (mA >= MROWS) { rrA = 0; ttA = 0; }
    const uint32_t abase = (uint32_t)(rrA * ROWEL + ttA * TS) * 2;
    const int hi8 = (lane >> 4) * 8;
    const uint32_t bbase = (uint32_t)((lane & 7) * KP * 2 + (lane >> 3) * 16);
    const int rE = w * 16 + (lane >> 2);
    const int ql = lane & 3;

    int sidx = 0;
    for (int s = 0; s < S; ++s) {
        if (s + 1 < S) CPWAIT1(); else CPWAIT0();
        __syncthreads();
        if (s + 2 < S) {
            STAGE_X((sidx + 2) % 3, s + 2);
        }

        const uint32_t xb = sb + (uint32_t)sidx * XSZ;
        float acc[16][4];
#pragma unroll
        for (int nt = 0; nt < 16; ++nt)
#pragma unroll
            for (int q = 0; q < 4; ++q) acc[nt][q] = 0.0f;

#pragma unroll
        for (int kc = 0; kc < KM / 32; ++kc) {
            uint32_t ah[2][4];
#pragma unroll
            for (int s2 = 0; s2 < 2; ++s2) {
                const int e0 = (2 * kc + s2) * 16 + hi8;
                const uint32_t off = (uint32_t)((e0 / CIN) * TS + (e0 % CIN)) * 2;
                LDSM4(ah[s2], xb + abase + off);
            }
#pragma unroll
            for (int nt = 0; nt < 16; ++nt) {
                uint32_t bh[4];
                LDSM4(bh, sb + WH + bbase + (uint32_t)(nt * 8 * KP * 2 + kc * 64));
                mma_f16(acc[nt], ah[0], bh[0], bh[1]);
                mma_f16(acc[nt], ah[1], bh[2], bh[3]);
            }
        }

        const long r0s = base_r0 + (long)s * G;
#pragma unroll
        for (int hf = 0; hf < 2; ++hf) {
            const int m = rE + hf * 8;
            const int rr = m / TOUT, tt = m % TOUT;
            const long gr = r0s + rr;
            if (m < MROWS && gr < R_TOTAL) {
                uint32_t pkd[8];
#pragma unroll
                for (int j = 0; j < 8; ++j) {
                    float yy[2];
#pragma unroll
                    for (int h = 0; h < 2; ++h) {
                        const int nt = 2 * j + h;
                        const int c = nt * 4 + ql;
                        const float2 bb = *(const float2*)(sm + BIAS + c * 8);
                        const float temp = acc[nt][hf * 2 + 0] + bb.x;
                        const float gate = acc[nt][hf * 2 + 1] + bb.y;
                        float y = temp * fast_sigmoid(gate);
                        yy[h] = (y > 0.0f) ? y : 0.0f;
                    }
                    __half2 h2 = __floats2half2_rn(yy[0], yy[1]);
                    pkd[j] = *(uint32_t*)&h2;
                }
                __half* dst = Yh + ((size_t)gr * TOUT + tt) * 64 + ql * 16;
                *(uint4*)dst       = make_uint4(pkd[0], pkd[1], pkd[2], pkd[3]);
                *(uint4*)(dst + 8) = make_uint4(pkd[4], pkd[5], pkd[6], pkd[7]);
            }
        }
        sidx = (sidx + 1) % 3;
    }
#undef STAGE_X
}

// ------- einsum GEMM: 3-stage cp.async ring, warps 2m x 4n, BM=BN=128 -------
template <int F>
__global__ __launch_bounds__(256, 2) void gemm_mma_kernel(
    const __half* __restrict__ Ah_g, const __half* __restrict__ Uh_g,
    __half* __restrict__ Ch_g)
{
    constexpr uint32_t BH = 128 * 80;        // 10240
    constexpr uint32_t STG = 2 * BH;         // 20480 B/stage
    extern __shared__ __align__(128) char smc[];
    const uint32_t sb = smem_u32(smc);

    const int tid = threadIdx.x, w = tid >> 5, lane = tid & 31;
    const int wm = w >> 2, wn = w & 3;
    const int m0 = blockIdx.x * 128, n0 = blockIdx.y * 128;

    const __half* Ab = Ah_g + (size_t)m0 * 2048;
    const __half* Bb = Uh_g + (size_t)n0 * 2048;

    const int ra = tid >> 1;
    const uint32_t acb = (tid & 1) * 32;
    const int ace = (tid & 1) * 16;

#define LOAD_STAGE(buf, k0) do {                                               \
    const uint32_t st_ = sb + (uint32_t)(buf) * STG;                           \
    CP16(st_ + ra * 80 + acb,           Ab + (size_t)ra * 2048 + (k0) + ace);  \
    CP16(st_ + ra * 80 + acb + 16,      Ab + (size_t)ra * 2048 + (k0) + ace + 8);\
    CP16(st_ + BH + ra * 80 + acb,      Bb + (size_t)ra * 2048 + (k0) + ace);  \
    CP16(st_ + BH + ra * 80 + acb + 16, Bb + (size_t)ra * 2048 + (k0) + ace + 8);\
    CPCOMMIT();                                                                \
} while (0)

    float acc[4][4][4];
#pragma unroll
    for (int mi = 0; mi < 4; ++mi)
#pragma unroll
        for (int ni = 0; ni < 4; ++ni)
#pragma unroll
            for (int q = 0; q < 4; ++q) acc[mi][ni][q] = 0.0f;

    LOAD_STAGE(0, 0);
    LOAD_STAGE(1, 32);
    const uint32_t aoff = (uint32_t)((wm * 64 + (lane & 15)) * 80 + (lane >> 4) * 16);
    const uint32_t boff = (uint32_t)((wn * 32 + (lane & 7)) * 80 + (lane >> 3) * 16);

    int sidx = 0;
    for (int it = 0; it < 64; ++it) {
        if (it + 1 < 64) CPWAIT1(); else CPWAIT0();
        __syncthreads();
        if (it + 2 < 64) LOAD_STAGE((sidx + 2) % 3, (it + 2) * 32);

        const uint32_t st = sb + (uint32_t)sidx * STG;
        uint32_t bF[4][4];
#pragma unroll
        for (int ni = 0; ni < 4; ++ni)
            LDSM4(bF[ni], st + BH + boff + ni * 8 * 80);
#pragma unroll
        for (int mi = 0; mi < 4; ++mi) {
            uint32_t aF[2][4];
            LDSM4(aF[0], st + aoff + mi * 16 * 80);
            LDSM4(aF[1], st + aoff + mi * 16 * 80 + 32);
#pragma unroll
            for (int ni = 0; ni < 4; ++ni) {
                mma_f16(acc[mi][ni], aF[0], bF[ni][0], bF[ni][1]);
                mma_f16(acc[mi][ni], aF[1], bF[ni][2], bF[ni][3]);
            }
        }
        sidx = (sidx + 1) % 3;
    }

    const int cbase = 2 * (lane & 3);
#pragma unroll
    for (int mi = 0; mi < 4; ++mi) {
        const int mr = m0 + wm * 64 + mi * 16 + (lane >> 2);
#pragma unroll
        for (int ni = 0; ni < 4; ++ni) {
            const int n = n0 + wn * 32 + ni * 8 + cbase;
            const int z = n / F, f = n - z * F;
            __half* H0 = Ch_g + ((size_t)z * 2048 + mr) * F + f;
            *(__half2*)H0 = __floats2half2_rn(fmaxf(acc[mi][ni][0], 0.0f),
                                              fmaxf(acc[mi][ni][1], 0.0f));
            *(__half2*)(H0 + 8 * (size_t)F) =
                __floats2half2_rn(fmaxf(acc[mi][ni][2], 0.0f),
                                  fmaxf(acc[mi][ni][3], 0.0f));
        }
    }
#undef LOAD_STAGE
}

// ---------------- FC (fp16 permuted input) ----------------
__global__ __launch_bounds__(256) void fc_kernel(const __half* __restrict__ X,
    const float* __restrict__ W, const float* __restrict__ bias, float* __restrict__ out)
{
    const int lane = threadIdx.x;
    const long row = (long)blockIdx.x * blockDim.y + threadIdx.y;
    const __half2* x2 = (const __half2*)(X + row * 896);
    float acc[12];
#pragma unroll
    for (int p = 0; p < 12; ++p) acc[p] = 0.0f;
    for (int e2 = lane; e2 < 448; e2 += 32) {
        const float2 f = __half22float2(x2[e2]);
        const int t = e2 >> 5;
        const int p2 = (e2 & 31) * 2;
        const int cin = (p2 >> 4) + (p2 & 15) * 4;
        const float* w0 = W + (size_t)(t * 64 + cin) * 12;
#pragma unroll
        for (int p = 0; p < 12; ++p)
            acc[p] = fmaf(f.x, w0[p], fmaf(f.y, w0[48 + p], acc[p]));
    }
#pragma unroll
    for (int off = 16; off > 0; off >>= 1)
#pragma unroll
        for (int p = 0; p < 12; ++p) acc[p] += __shfl_down_sync(0xffffffffu, acc[p], off);
    if (lane == 0)
#pragma unroll
        for (int p = 0; p < 12; ++p) out[row * 12 + p] = acc[p] + bias[p];
}

// ---------------- launch ----------------
extern "C" void kernel_launch(void* const* d_in, const int* in_sizes, int n_in,
                              void* d_out, int out_size)
{
    const float* x       = (const float*)d_in[0];
    const float* A_hat   = (const float*)d_in[1];
    const float* tb1_w   = (const float*)d_in[2];
    const float* tb1_b   = (const float*)d_in[3];
    const float* theta1  = (const float*)d_in[4];
    const float* tb2_w   = (const float*)d_in[5];
    const float* tb2_b   = (const float*)d_in[6];
    const float* tb3_w   = (const float*)d_in[7];
    const float* tb3_b   = (const float*)d_in[8];
    const float* theta2  = (const float*)d_in[9];
    const float* tb4_w   = (const float*)d_in[10];
    const float* tb4_b   = (const float*)d_in[11];
    const float* tb5_w   = (const float*)d_in[12];
    const float* tb5_b   = (const float*)d_in[13];
    const float* fully_w = (const float*)d_in[14];
    const float* fully_b = (const float*)d_in[15];
    float* out = (float*)d_out;

    float *bufC;
    __half *Ah, *Uh, *Ch, *Xh, *Yh, *Wth;
    float2 *Wp, *bp;
    cudaGetSymbolAddress((void**)&bufC, g_bufC);
    cudaGetSymbolAddress((void**)&Ah, g_Ah);
    cudaGetSymbolAddress((void**)&Uh, g_Uh);
    cudaGetSymbolAddress((void**)&Ch, g_Ch);
    cudaGetSymbolAddress((void**)&Xh, g_Xh);
    cudaGetSymbolAddress((void**)&Yh, g_Yh);
    cudaGetSymbolAddress((void**)&Wth, g_Wth);
    cudaGetSymbolAddress((void**)&Wp, g_Wp);
    cudaGetSymbolAddress((void**)&bp, g_bp);

    constexpr int WS = 128 * 192;
    constexpr int SMEM_G = 3 * 20480;   // 61440
    constexpr int SM_TB2 = 3 * 6400  + 128 * 72 * 2  + 512;   // 38144
    constexpr int SM_TB3 = 3 * 20224 + 128 * 200 * 2 + 512;   // 112384
    constexpr int SM_TB4 = 3 * 6976  + 128 * 72 * 2  + 512;   // 39872
    constexpr int SM_TB5 = 3 * 20800 + 128 * 200 * 2 + 512;   // 114112
    cudaFuncSetAttribute(gemm_mma_kernel<352>, cudaFuncAttributeMaxDynamicSharedMemorySize, SMEM_G);
    cudaFuncSetAttribute(gemm_mma_kernel<288>, cudaFuncAttributeMaxDynamicSharedMemorySize, SMEM_G);
    cudaFuncSetAttribute(convmma_kernel<16, 22, 6, 8>, cudaFuncAttributeMaxDynamicSharedMemorySize, SM_TB2);
    cudaFuncSetAttribute(convmma_kernel<64, 20, 7, 8>, cudaFuncAttributeMaxDynamicSharedMemorySize, SM_TB3);
    cudaFuncSetAttribute(convmma_kernel<16, 18, 8, 8>, cudaFuncAttributeMaxDynamicSharedMemorySize, SM_TB4);
    cudaFuncSetAttribute(convmma_kernel<64, 16, 9, 8>, cudaFuncAttributeMaxDynamicSharedMemorySize, SM_TB5);

    // prep (1 launch; also copies A_hat into out tail)
    prep_kernel<<<NNODE * NNODE / 1024, 256>>>(A_hat, Ah,
        tb1_w, tb1_b, tb2_w, tb2_b, tb3_w, tb3_b, tb4_w, tb4_b, tb5_w, tb5_b,
        Wp, Wth, (float2*)bp, out + (long)R_TOTAL * 12);

    // block 1
    timeblock_kernel<2, 24><<<R_TOTAL / 2, dim3(64, 2)>>>(x, Wp, (float2*)bp + 0 * 64, theta1, bufC);
    tsplitU_kernel<352><<<dim3(64, 11, BATCH), 256>>>(bufC, Uh);
    gemm_mma_kernel<352><<<dim3(16, (BATCH * 352) / 128), 256, SMEM_G>>>(Ah, Uh, Ch);
    convmma_kernel<16, 22, 6, 8><<<(R_TOTAL + 47) / 48, 256, SM_TB2>>>(
        Ch, Wth + 0 * WS, (float2*)bp + 1 * 64, Xh);

    // block 2
    convmma_kernel<64, 20, 7, 8><<<(R_TOTAL + 55) / 56, 256, SM_TB3>>>(
        Xh, Wth + 1 * WS, (float2*)bp + 2 * 64, Yh);
    theta_tsplit_kernel<<<dim3(256, 16), 256>>>(Yh, theta2, Uh);
    gemm_mma_kernel<288><<<dim3(16, (BATCH * 288) / 128), 256, SMEM_G>>>(Ah, Uh, Ch);
    convmma_kernel<16, 18, 8, 8><<<R_TOTAL / 64, 256, SM_TB4>>>(
        Ch, Wth + 2 * WS, (float2*)bp + 3 * 64, Xh);

    // head
    convmma_kernel<64, 16, 9, 8><<<(R_TOTAL + 71) / 72, 256, SM_TB5>>>(
        Xh, Wth + 3 * WS, (float2*)bp + 4 * 64, Yh);
    fc_kernel<<<R_TOTAL / 8, dim3(32, 8)>>>(Yh, fully_w, fully_b, out);
}